// round 11
// baseline (speedup 1.0000x reference)
#include <cuda_runtime.h>
#include <math.h>
#include <stdint.h>

#define GRID_RES 256
#define CELLSZ   0.015f
#define NS       64
#define MIN_BETA 0.015f

__device__ __forceinline__ void cp8(uint32_t saddr, const void* gaddr) {
    asm volatile("cp.async.ca.shared.global [%0], [%1], 8;\n"
                 :: "r"(saddr), "l"(gaddr));
}

// 128 threads = 4 warps = 2 rays per block; thread-per-sample.
// cp.async gathers into smem: high MLP without holding dest registers.
__global__ void __launch_bounds__(128, 10)
plainvoxels_render_kernel(
    const float* __restrict__ grid,        // [256,256,256,5]
    const float* __restrict__ beta,        // [1]
    const float* __restrict__ rays_o,      // [N,3]
    const float* __restrict__ rays_d,      // [N,3]
    const float* __restrict__ rays_d_norm, // [N,1]
    const float* __restrict__ nearp,       // [1]
    const float* __restrict__ farp,        // [1]
    float* __restrict__ out_rgb,     // [N,3]
    float* __restrict__ out_depth,   // [N,1]
    float* __restrict__ out_normals, // [N,3]
    float* __restrict__ out_acc,     // [N,1]
    float* __restrict__ out_grads,   // [N*NS,3]
    float* __restrict__ out_near,    // [N,1]
    float* __restrict__ out_far,     // [N,1]
    int N)
{
    // [slot][tid]: lane-consecutive 8B -> conflict-free LDS.64
    __shared__ float2 sw[20][128];
    __shared__ float warp_tot[4];
    __shared__ float red[4][8];

    const int tid  = threadIdx.x;
    const int warp = tid >> 5;
    const int lane = tid & 31;
    const int s    = tid & 63;
    const int nray = blockIdx.x * 2 + (tid >> 6);
    const bool valid = (nray < N);
    const int n = valid ? nray : (N - 1);

    const float ORIGIN = __fmul_rn(__fmul_rn(-0.5f, (float)GRID_RES), CELLSZ);

    const float ox = rays_o[3*n+0], oy = rays_o[3*n+1], oz = rays_o[3*n+2];
    const float dx = rays_d[3*n+0], dy = rays_d[3*n+1], dz = rays_d[3*n+2];
    const float nr = nearp[0], fr = farp[0];
    const float dt = __fdiv_rn(__fsub_rn(fr, nr), (float)NS);

    // exact reference rounding (floor/index path must be bit-exact)
    const float t_n   = __fadd_rn(nr, __fmul_rn((float)s, dt));
    const float t_f   = __fadd_rn(t_n, dt);
    const float t_mid = __fmul_rn(0.5f, __fadd_rn(t_n, t_f));
    const float px = __fadd_rn(ox, __fmul_rn(t_mid, dx));
    const float py = __fadd_rn(oy, __fmul_rn(t_mid, dy));
    const float pz = __fadd_rn(oz, __fmul_rn(t_mid, dz));

    const float ux = __fdiv_rn(__fsub_rn(px, ORIGIN), CELLSZ);
    const float uy = __fdiv_rn(__fsub_rn(py, ORIGIN), CELLSZ);
    const float uz = __fdiv_rn(__fsub_rn(pz, ORIGIN), CELLSZ);

    const int ix = min(max((int)floorf(ux), 0), GRID_RES - 2);
    const int iy = min(max((int)floorf(uy), 0), GRID_RES - 2);
    const int iz = min(max((int)floorf(uz), 0), GRID_RES - 2);

    const int base = ((ix * GRID_RES + iy) * GRID_RES + iz) * 5;
    const int OX = GRID_RES * GRID_RES * 5;   // 327680 (even)
    const int OY = GRID_RES * 5;              // 1280   (even)

    // z-pair windows, 8B aligned: [e&~1, e&~1 + 10 floats)
    const float2* q0 = (const float2*)(grid + ((base)           & ~1));
    const float2* q1 = (const float2*)(grid + ((base + OY)      & ~1));
    const float2* q2 = (const float2*)(grid + ((base + OX)      & ~1));
    const float2* q3 = (const float2*)(grid + ((base + OX + OY) & ~1));

    // Issue all 20 cp.asyncs (no dest registers held).
    const uint32_t sb = (uint32_t)__cvta_generic_to_shared(&sw[0][0]) + (uint32_t)tid * 8u;
    #pragma unroll
    for (int j = 0; j < 5; j++) cp8(sb + (0*5 + j) * 1024u, q0 + j);
    #pragma unroll
    for (int j = 0; j < 5; j++) cp8(sb + (1*5 + j) * 1024u, q1 + j);
    #pragma unroll
    for (int j = 0; j < 5; j++) cp8(sb + (2*5 + j) * 1024u, q2 + j);
    #pragma unroll
    for (int j = 0; j < 5; j++) cp8(sb + (3*5 + j) * 1024u, q3 + j);
    asm volatile("cp.async.commit_group;\n" ::: "memory");

    // Overlap: fractions, weights, mask while copies are in flight.
    const float fx = __fsub_rn(ux, (float)ix);
    const float fy = __fsub_rn(uy, (float)iy);
    const float fz = __fsub_rn(uz, (float)iz);
    const float gx = 1.0f - fx, gy = 1.0f - fy, gz = 1.0f - fz;
    const bool mask = (ux >= 0.0f) && (ux <= (float)(GRID_RES-1)) &&
                      (uy >= 0.0f) && (uy <= (float)(GRID_RES-1)) &&
                      (uz >= 0.0f) && (uz <= (float)(GRID_RES-1));
    const bool ksel = (base & 1) != 0;

    asm volatile("cp.async.wait_group 0;\n" ::: "memory");
    // Each thread reads only its own slots -> no __syncthreads needed.

    float feat0 = 0.f, feat1 = 0.f, feat2 = 0.f, feat3 = 0.f;
    float dfx = 0.f, dfy = 0.f, dfzv = 0.f;

    #pragma unroll
    for (int p = 0; p < 4; p++) {
        float w[10];
        #pragma unroll
        for (int j = 0; j < 5; j++) {
            const float2 t = sw[p*5 + j][tid];
            w[2*j]   = t.x;
            w[2*j+1] = t.y;
        }

        // corner (dx,dy,0) chans = w[k..k+3], corner (dx,dy,1) = w[k+5..k+8]
        float v0[4], v1[4];
        #pragma unroll
        for (int j = 0; j < 4; j++) v0[j] = ksel ? w[j + 1] : w[j];
        #pragma unroll
        for (int j = 0; j < 4; j++) v1[j] = ksel ? w[j + 6] : w[j + 5];

        const float wx  = (p & 2) ? fx : gx;
        const float wy  = (p & 1) ? fy : gy;
        const float wxy = wx * wy;

        const float zb0 = v0[0] * gz + v1[0] * fz;
        const float zb1 = v0[1] * gz + v1[1] * fz;
        const float zb2 = v0[2] * gz + v1[2] * fz;
        const float zb3 = v0[3] * gz + v1[3] * fz;

        feat0 += zb0 * wxy;
        feat1 += zb1 * wxy;
        feat2 += zb2 * wxy;
        feat3 += zb3 * wxy;
        dfzv  += (v1[0] - v0[0]) * wxy;
        dfx   += (p & 2) ? (zb0 * wy) : (-zb0 * wy);
        dfy   += (p & 1) ? (zb0 * wx) : (-zb0 * wx);
    }

    const float sdf = feat0;
    const float grx = __fdiv_rn(dfx,  CELLSZ);
    const float gry = __fdiv_rn(dfy,  CELLSZ);
    const float grz = __fdiv_rn(dfzv, CELLSZ);

    if (valid) {
        const int m = n * NS + s;
        out_grads[3*m+0] = grx;
        out_grads[3*m+1] = gry;
        out_grads[3*m+2] = grz;
    }

    // unit normal (IEEE ops)
    const float gl = __fsqrt_rn(__fadd_rn(__fadd_rn(__fmul_rn(grx,grx),
                        __fmul_rn(gry,gry)), __fmul_rn(grz,grz)));
    const float den = fmaxf(gl, 1e-12f);
    const float nx = __fdiv_rn(grx, den);
    const float ny = __fdiv_rn(gry, den);
    const float nz = __fdiv_rn(grz, den);

    // Laplace CDF density
    const float beta_eff = MIN_BETA + fabsf(beta[0]);
    const float inv_beta = 1.0f / beta_eff;
    const float sgn = (sdf > 0.0f) ? 1.0f : ((sdf < 0.0f) ? -1.0f : 0.0f);
    float sigma = inv_beta * (0.5f + 0.5f * sgn * expm1f(-fabsf(sdf) * inv_beta));
    if (!mask) sigma = 0.0f;
    const float tau = sigma * dt;

    // ---- 2-warp exclusive prefix of tau over 64 samples ----
    float x = tau;
    #pragma unroll
    for (int o = 1; o < 32; o <<= 1) {
        float y = __shfl_up_sync(0xFFFFFFFFu, x, o);
        if (lane >= o) x += y;
    }
    if (lane == 31) warp_tot[warp] = x;
    __syncthreads();
    float excl = x - tau;
    if (s >= 32) excl += warp_tot[warp - 1];

    const float T = expf(-excl);
    const float a = -expm1f(-tau);
    const float w = T * a;

    // ---- composite ----
    float acc[8];
    acc[0] = w * feat1;
    acc[1] = w * feat2;
    acc[2] = w * feat3;
    acc[3] = w * nx;
    acc[4] = w * ny;
    acc[5] = w * nz;
    acc[6] = w * t_mid;
    acc[7] = w;

    #pragma unroll
    for (int o = 16; o >= 1; o >>= 1) {
        #pragma unroll
        for (int k = 0; k < 8; k++)
            acc[k] += __shfl_xor_sync(0xFFFFFFFFu, acc[k], o);
    }
    if (lane == 0) {
        #pragma unroll
        for (int k = 0; k < 8; k++) red[warp][k] = acc[k];
    }
    __syncthreads();

    if ((tid & 63) == 0 && valid) {
        float r0 = red[warp][0] + red[warp+1][0];
        float r1 = red[warp][1] + red[warp+1][1];
        float r2 = red[warp][2] + red[warp+1][2];
        float r3 = red[warp][3] + red[warp+1][3];
        float r4 = red[warp][4] + red[warp+1][4];
        float r5 = red[warp][5] + red[warp+1][5];
        float r6 = red[warp][6] + red[warp+1][6];
        float r7 = red[warp][7] + red[warp+1][7];
        const float rdn = rays_d_norm[n];
        out_rgb[3*n+0] = r0;
        out_rgb[3*n+1] = r1;
        out_rgb[3*n+2] = r2;
        out_depth[n]   = __fdiv_rn(r6, rdn);
        out_normals[3*n+0] = r3;
        out_normals[3*n+1] = r4;
        out_normals[3*n+2] = r5;
        out_acc[n]     = r7;
        out_near[n]    = __fdiv_rn(nr, rdn);
        out_far[n]     = __fdiv_rn(fr, rdn);
    }
}

extern "C" void kernel_launch(void* const* d_in, const int* in_sizes, int n_in,
                              void* d_out, int out_size) {
    const float* grid        = (const float*)d_in[0];
    const float* beta        = (const float*)d_in[1];
    const float* rays_o      = (const float*)d_in[2];
    const float* rays_d      = (const float*)d_in[3];
    const float* rays_d_norm = (const float*)d_in[4];
    const float* nearp       = (const float*)d_in[5];
    const float* farp        = (const float*)d_in[6];

    const int N = in_sizes[2] / 3;

    float* out = (float*)d_out;
    float* out_rgb     = out;
    float* out_depth   = out_rgb + (size_t)3 * N;
    float* out_normals = out_depth + N;
    float* out_acc     = out_normals + (size_t)3*N;
    float* out_grads   = out_acc + N;
    float* out_near    = out_grads + (size_t)3 * N * NS;
    float* out_far     = out_near + N;

    const int threads = 128;
    const int blocks  = (N * NS + threads - 1) / threads;
    plainvoxels_render_kernel<<<blocks, threads>>>(
        grid, beta, rays_o, rays_d, rays_d_norm, nearp, farp,
        out_rgb, out_depth, out_normals, out_acc, out_grads, out_near, out_far, N);
}

// round 13
// speedup vs baseline: 2.1814x; 2.1814x over previous
#include <cuda_runtime.h>
#include <math.h>

#define GRID_RES 256
#define CELLSZ   0.015f
#define NS       64
#define MIN_BETA 0.015f

// 128 threads = 4 warps = 2 rays per block; thread-per-sample.
// 8 blocks/SM min -> 64-reg cap; 20 LDG.64s front-batched, round-robin
// across the 4 windows for earliest distinct-line miss issue.
__global__ void __launch_bounds__(128, 8)
plainvoxels_render_kernel(
    const float* __restrict__ grid,        // [256,256,256,5]
    const float* __restrict__ beta,        // [1]
    const float* __restrict__ rays_o,      // [N,3]
    const float* __restrict__ rays_d,      // [N,3]
    const float* __restrict__ rays_d_norm, // [N,1]
    const float* __restrict__ nearp,       // [1]
    const float* __restrict__ farp,        // [1]
    float* __restrict__ out_rgb,     // [N,3]
    float* __restrict__ out_depth,   // [N,1]
    float* __restrict__ out_normals, // [N,3]
    float* __restrict__ out_acc,     // [N,1]
    float* __restrict__ out_grads,   // [N*NS,3]
    float* __restrict__ out_near,    // [N,1]
    float* __restrict__ out_far,     // [N,1]
    int N)
{
    __shared__ float warp_tot[4];
    __shared__ float red[4][8];

    const int tid  = threadIdx.x;
    const int warp = tid >> 5;
    const int lane = tid & 31;
    const int s    = tid & 63;
    const int nray = blockIdx.x * 2 + (tid >> 6);
    const bool valid = (nray < N);
    const int n = valid ? nray : (N - 1);

    const float ORIGIN = __fmul_rn(__fmul_rn(-0.5f, (float)GRID_RES), CELLSZ);

    const float ox = rays_o[3*n+0], oy = rays_o[3*n+1], oz = rays_o[3*n+2];
    const float dx = rays_d[3*n+0], dy = rays_d[3*n+1], dz = rays_d[3*n+2];
    const float nr = nearp[0], fr = farp[0];
    const float dt = __fdiv_rn(__fsub_rn(fr, nr), (float)NS);

    // exact reference rounding (floor/index path must be bit-exact)
    const float t_n   = __fadd_rn(nr, __fmul_rn((float)s, dt));
    const float t_f   = __fadd_rn(t_n, dt);
    const float t_mid = __fmul_rn(0.5f, __fadd_rn(t_n, t_f));
    const float px = __fadd_rn(ox, __fmul_rn(t_mid, dx));
    const float py = __fadd_rn(oy, __fmul_rn(t_mid, dy));
    const float pz = __fadd_rn(oz, __fmul_rn(t_mid, dz));

    const float ux = __fdiv_rn(__fsub_rn(px, ORIGIN), CELLSZ);
    const float uy = __fdiv_rn(__fsub_rn(py, ORIGIN), CELLSZ);
    const float uz = __fdiv_rn(__fsub_rn(pz, ORIGIN), CELLSZ);

    // indices only (fractions/mask materialized after the load window)
    const int ix = min(max((int)floorf(ux), 0), GRID_RES - 2);
    const int iy = min(max((int)floorf(uy), 0), GRID_RES - 2);
    const int iz = min(max((int)floorf(uz), 0), GRID_RES - 2);

    const int base = ((ix * GRID_RES + iy) * GRID_RES + iz) * 5;
    const int OX = GRID_RES * GRID_RES * 5;   // 327680 (even)
    const int OY = GRID_RES * 5;              // 1280   (even)

    // z-pair windows, 8B aligned: [e&~1, e&~1 + 10 floats)
    const float2* q0 = (const float2*)(grid + ((base)           & ~1));
    const float2* q1 = (const float2*)(grid + ((base + OY)      & ~1));
    const float2* q2 = (const float2*)(grid + ((base + OX)      & ~1));
    const float2* q3 = (const float2*)(grid + ((base + OX + OY) & ~1));

    // Front-batch ALL 20 LDG.64s, round-robin across windows so the 4
    // distinct line groups miss as early as possible.
    float2 W[4][5];
    #pragma unroll
    for (int j = 0; j < 5; j++) {
        W[0][j] = __ldg(q0 + j);
        W[1][j] = __ldg(q1 + j);
        W[2][j] = __ldg(q2 + j);
        W[3][j] = __ldg(q3 + j);
    }

    // Materialize fractions, weights, mask (identical values/rounding).
    const float fx = __fsub_rn(ux, (float)ix);
    const float fy = __fsub_rn(uy, (float)iy);
    const float fz = __fsub_rn(uz, (float)iz);
    const float gx = 1.0f - fx, gy = 1.0f - fy, gz = 1.0f - fz;
    const bool mask = (ux >= 0.0f) && (ux <= (float)(GRID_RES-1)) &&
                      (uy >= 0.0f) && (uy <= (float)(GRID_RES-1)) &&
                      (uz >= 0.0f) && (uz <= (float)(GRID_RES-1));
    const bool ksel = (base & 1) != 0;

    // Accumulate trilinear + gradient pair-by-pair so window regs die early.
    float feat0 = 0.f, feat1 = 0.f, feat2 = 0.f, feat3 = 0.f;
    float dfx = 0.f, dfy = 0.f, dfzv = 0.f;

    #pragma unroll
    for (int p = 0; p < 4; p++) {
        float w[10];
        w[0] = W[p][0].x; w[1] = W[p][0].y;
        w[2] = W[p][1].x; w[3] = W[p][1].y;
        w[4] = W[p][2].x; w[5] = W[p][2].y;
        w[6] = W[p][3].x; w[7] = W[p][3].y;
        w[8] = W[p][4].x; w[9] = W[p][4].y;

        // corner (dx,dy,0) chans = w[k..k+3], corner (dx,dy,1) = w[k+5..k+8]
        float v0[4], v1[4];
        #pragma unroll
        for (int j = 0; j < 4; j++) v0[j] = ksel ? w[j + 1] : w[j];
        #pragma unroll
        for (int j = 0; j < 4; j++) v1[j] = ksel ? w[j + 6] : w[j + 5];

        const float wx  = (p & 2) ? fx : gx;
        const float wy  = (p & 1) ? fy : gy;
        const float wxy = wx * wy;

        const float zb0 = v0[0] * gz + v1[0] * fz;
        const float zb1 = v0[1] * gz + v1[1] * fz;
        const float zb2 = v0[2] * gz + v1[2] * fz;
        const float zb3 = v0[3] * gz + v1[3] * fz;

        feat0 += zb0 * wxy;
        feat1 += zb1 * wxy;
        feat2 += zb2 * wxy;
        feat3 += zb3 * wxy;
        dfzv  += (v1[0] - v0[0]) * wxy;
        dfx   += (p & 2) ? (zb0 * wy) : (-zb0 * wy);
        dfy   += (p & 1) ? (zb0 * wx) : (-zb0 * wx);
    }

    const float sdf = feat0;
    const float grx = __fdiv_rn(dfx,  CELLSZ);
    const float gry = __fdiv_rn(dfy,  CELLSZ);
    const float grz = __fdiv_rn(dfzv, CELLSZ);

    if (valid) {
        const int m = n * NS + s;
        // streaming stores: written once, never read -> keep L2 for the grid
        __stcs(&out_grads[3*m+0], grx);
        __stcs(&out_grads[3*m+1], gry);
        __stcs(&out_grads[3*m+2], grz);
    }

    // unit normal (IEEE ops)
    const float gl = __fsqrt_rn(__fadd_rn(__fadd_rn(__fmul_rn(grx,grx),
                        __fmul_rn(gry,gry)), __fmul_rn(grz,grz)));
    const float den = fmaxf(gl, 1e-12f);
    const float nx = __fdiv_rn(grx, den);
    const float ny = __fdiv_rn(gry, den);
    const float nz = __fdiv_rn(grz, den);

    // Laplace CDF density
    const float beta_eff = MIN_BETA + fabsf(beta[0]);
    const float inv_beta = 1.0f / beta_eff;
    const float sgn = (sdf > 0.0f) ? 1.0f : ((sdf < 0.0f) ? -1.0f : 0.0f);
    float sigma = inv_beta * (0.5f + 0.5f * sgn * expm1f(-fabsf(sdf) * inv_beta));
    if (!mask) sigma = 0.0f;
    const float tau = sigma * dt;

    // ---- 2-warp exclusive prefix of tau over 64 samples ----
    float x = tau;
    #pragma unroll
    for (int o = 1; o < 32; o <<= 1) {
        float y = __shfl_up_sync(0xFFFFFFFFu, x, o);
        if (lane >= o) x += y;
    }
    if (lane == 31) warp_tot[warp] = x;
    __syncthreads();
    float excl = x - tau;
    if (s >= 32) excl += warp_tot[warp - 1];

    const float T = expf(-excl);
    const float a = -expm1f(-tau);
    const float w = T * a;

    // ---- composite ----
    float acc[8];
    acc[0] = w * feat1;
    acc[1] = w * feat2;
    acc[2] = w * feat3;
    acc[3] = w * nx;
    acc[4] = w * ny;
    acc[5] = w * nz;
    acc[6] = w * t_mid;
    acc[7] = w;

    #pragma unroll
    for (int o = 16; o >= 1; o >>= 1) {
        #pragma unroll
        for (int k = 0; k < 8; k++)
            acc[k] += __shfl_xor_sync(0xFFFFFFFFu, acc[k], o);
    }
    if (lane == 0) {
        #pragma unroll
        for (int k = 0; k < 8; k++) red[warp][k] = acc[k];
    }
    __syncthreads();

    if ((tid & 63) == 0 && valid) {
        float r0 = red[warp][0] + red[warp+1][0];
        float r1 = red[warp][1] + red[warp+1][1];
        float r2 = red[warp][2] + red[warp+1][2];
        float r3 = red[warp][3] + red[warp+1][3];
        float r4 = red[warp][4] + red[warp+1][4];
        float r5 = red[warp][5] + red[warp+1][5];
        float r6 = red[warp][6] + red[warp+1][6];
        float r7 = red[warp][7] + red[warp+1][7];
        const float rdn = rays_d_norm[n];
        __stcs(&out_rgb[3*n+0], r0);
        __stcs(&out_rgb[3*n+1], r1);
        __stcs(&out_rgb[3*n+2], r2);
        __stcs(&out_depth[n],   __fdiv_rn(r6, rdn));
        __stcs(&out_normals[3*n+0], r3);
        __stcs(&out_normals[3*n+1], r4);
        __stcs(&out_normals[3*n+2], r5);
        __stcs(&out_acc[n],  r7);
        __stcs(&out_near[n], __fdiv_rn(nr, rdn));
        __stcs(&out_far[n],  __fdiv_rn(fr, rdn));
    }
}

extern "C" void kernel_launch(void* const* d_in, const int* in_sizes, int n_in,
                              void* d_out, int out_size) {
    const float* grid        = (const float*)d_in[0];
    const float* beta        = (const float*)d_in[1];
    const float* rays_o      = (const float*)d_in[2];
    const float* rays_d      = (const float*)d_in[3];
    const float* rays_d_norm = (const float*)d_in[4];
    const float* nearp       = (const float*)d_in[5];
    const float* farp        = (const float*)d_in[6];

    const int N = in_sizes[2] / 3;

    float* out = (float*)d_out;
    float* out_rgb     = out;
    float* out_depth   = out_rgb + (size_t)3 * N;
    float* out_normals = out_depth + N;
    float* out_acc     = out_normals + (size_t)3*N;
    float* out_grads   = out_acc + N;
    float* out_near    = out_grads + (size_t)3 * N * NS;
    float* out_far     = out_near + N;

    const int threads = 128;
    const int blocks  = (N * NS + threads - 1) / threads;
    plainvoxels_render_kernel<<<blocks, threads>>>(
        grid, beta, rays_o, rays_d, rays_d_norm, nearp, farp,
        out_rgb, out_depth, out_normals, out_acc, out_grads, out_near, out_far, N);
}

// round 15
// speedup vs baseline: 2.1847x; 1.0015x over previous
#include <cuda_runtime.h>
#include <math.h>
#include <stdint.h>

#define GRID_RES 256
#define CELLSZ   0.015f
#define NS       64
#define MIN_BETA 0.015f

// L2 evict-last grid load via cache-hint policy descriptor (sm_103a-accepted
// form; the inline .L2::evict_last qualifier only exists for 256-bit loads).
__device__ __forceinline__ float2 ldg_el(const float2* p, uint64_t pol) {
    float2 r;
    asm volatile("ld.global.nc.L2::cache_hint.v2.f32 {%0,%1}, [%2], %3;"
                 : "=f"(r.x), "=f"(r.y) : "l"(p), "l"(pol));
    return r;
}

// 128 threads = 4 warps = 2 rays per block; thread-per-sample.
// 8 blocks/SM min -> 64-reg cap; 20 LDG.64s front-batched, round-robin
// across the 4 windows for earliest distinct-line miss issue.
__global__ void __launch_bounds__(128, 8)
plainvoxels_render_kernel(
    const float* __restrict__ grid,        // [256,256,256,5]
    const float* __restrict__ beta,        // [1]
    const float* __restrict__ rays_o,      // [N,3]
    const float* __restrict__ rays_d,      // [N,3]
    const float* __restrict__ rays_d_norm, // [N,1]
    const float* __restrict__ nearp,       // [1]
    const float* __restrict__ farp,        // [1]
    float* __restrict__ out_rgb,     // [N,3]
    float* __restrict__ out_depth,   // [N,1]
    float* __restrict__ out_normals, // [N,3]
    float* __restrict__ out_acc,     // [N,1]
    float* __restrict__ out_grads,   // [N*NS,3]
    float* __restrict__ out_near,    // [N,1]
    float* __restrict__ out_far,     // [N,1]
    int N)
{
    __shared__ float warp_tot[4];
    __shared__ float red[4][8];

    const int tid  = threadIdx.x;
    const int warp = tid >> 5;
    const int lane = tid & 31;
    const int s    = tid & 63;
    const int nray = blockIdx.x * 2 + (tid >> 6);
    const bool valid = (nray < N);
    const int n = valid ? nray : (N - 1);

    const float ORIGIN = __fmul_rn(__fmul_rn(-0.5f, (float)GRID_RES), CELLSZ);

    const float ox = rays_o[3*n+0], oy = rays_o[3*n+1], oz = rays_o[3*n+2];
    const float dx = rays_d[3*n+0], dy = rays_d[3*n+1], dz = rays_d[3*n+2];
    const float nr = nearp[0], fr = farp[0];
    const float dt = __fdiv_rn(__fsub_rn(fr, nr), (float)NS);

    // exact reference rounding (floor/index path must be bit-exact)
    const float t_n   = __fadd_rn(nr, __fmul_rn((float)s, dt));
    const float t_f   = __fadd_rn(t_n, dt);
    const float t_mid = __fmul_rn(0.5f, __fadd_rn(t_n, t_f));
    const float px = __fadd_rn(ox, __fmul_rn(t_mid, dx));
    const float py = __fadd_rn(oy, __fmul_rn(t_mid, dy));
    const float pz = __fadd_rn(oz, __fmul_rn(t_mid, dz));

    const float ux = __fdiv_rn(__fsub_rn(px, ORIGIN), CELLSZ);
    const float uy = __fdiv_rn(__fsub_rn(py, ORIGIN), CELLSZ);
    const float uz = __fdiv_rn(__fsub_rn(pz, ORIGIN), CELLSZ);

    // indices only (fractions/mask materialized after the load window)
    const int ix = min(max((int)floorf(ux), 0), GRID_RES - 2);
    const int iy = min(max((int)floorf(uy), 0), GRID_RES - 2);
    const int iz = min(max((int)floorf(uz), 0), GRID_RES - 2);

    const int base = ((ix * GRID_RES + iy) * GRID_RES + iz) * 5;
    const int OX = GRID_RES * GRID_RES * 5;   // 327680 (even)
    const int OY = GRID_RES * 5;              // 1280   (even)

    // z-pair windows, 8B aligned: [e&~1, e&~1 + 10 floats)
    const float2* q0 = (const float2*)(grid + ((base)           & ~1));
    const float2* q1 = (const float2*)(grid + ((base + OY)      & ~1));
    const float2* q2 = (const float2*)(grid + ((base + OX)      & ~1));
    const float2* q3 = (const float2*)(grid + ((base + OX + OY) & ~1));

    // evict-last policy for the grid loads
    uint64_t pol;
    asm volatile("createpolicy.fractional.L2::evict_last.b64 %0, 1.0;" : "=l"(pol));

    // Front-batch ALL 20 LDG.64s, round-robin across windows so the 4
    // distinct line groups miss as early as possible.
    float2 W[4][5];
    #pragma unroll
    for (int j = 0; j < 5; j++) {
        W[0][j] = ldg_el(q0 + j, pol);
        W[1][j] = ldg_el(q1 + j, pol);
        W[2][j] = ldg_el(q2 + j, pol);
        W[3][j] = ldg_el(q3 + j, pol);
    }

    // Materialize fractions, weights, mask (identical values/rounding).
    const float fx = __fsub_rn(ux, (float)ix);
    const float fy = __fsub_rn(uy, (float)iy);
    const float fz = __fsub_rn(uz, (float)iz);
    const float gx = 1.0f - fx, gy = 1.0f - fy, gz = 1.0f - fz;
    const bool mask = (ux >= 0.0f) && (ux <= (float)(GRID_RES-1)) &&
                      (uy >= 0.0f) && (uy <= (float)(GRID_RES-1)) &&
                      (uz >= 0.0f) && (uz <= (float)(GRID_RES-1));
    const bool ksel = (base & 1) != 0;

    // Accumulate trilinear + gradient pair-by-pair so window regs die early.
    float feat0 = 0.f, feat1 = 0.f, feat2 = 0.f, feat3 = 0.f;
    float dfx = 0.f, dfy = 0.f, dfzv = 0.f;

    #pragma unroll
    for (int p = 0; p < 4; p++) {
        float w[10];
        w[0] = W[p][0].x; w[1] = W[p][0].y;
        w[2] = W[p][1].x; w[3] = W[p][1].y;
        w[4] = W[p][2].x; w[5] = W[p][2].y;
        w[6] = W[p][3].x; w[7] = W[p][3].y;
        w[8] = W[p][4].x; w[9] = W[p][4].y;

        // corner (dx,dy,0) chans = w[k..k+3], corner (dx,dy,1) = w[k+5..k+8]
        float v0[4], v1[4];
        #pragma unroll
        for (int j = 0; j < 4; j++) v0[j] = ksel ? w[j + 1] : w[j];
        #pragma unroll
        for (int j = 0; j < 4; j++) v1[j] = ksel ? w[j + 6] : w[j + 5];

        const float wx  = (p & 2) ? fx : gx;
        const float wy  = (p & 1) ? fy : gy;
        const float wxy = wx * wy;

        const float zb0 = v0[0] * gz + v1[0] * fz;
        const float zb1 = v0[1] * gz + v1[1] * fz;
        const float zb2 = v0[2] * gz + v1[2] * fz;
        const float zb3 = v0[3] * gz + v1[3] * fz;

        feat0 += zb0 * wxy;
        feat1 += zb1 * wxy;
        feat2 += zb2 * wxy;
        feat3 += zb3 * wxy;
        dfzv  += (v1[0] - v0[0]) * wxy;
        dfx   += (p & 2) ? (zb0 * wy) : (-zb0 * wy);
        dfy   += (p & 1) ? (zb0 * wx) : (-zb0 * wx);
    }

    const float sdf = feat0;
    const float grx = __fdiv_rn(dfx,  CELLSZ);
    const float gry = __fdiv_rn(dfy,  CELLSZ);
    const float grz = __fdiv_rn(dfzv, CELLSZ);

    if (valid) {
        const int m = n * NS + s;
        // streaming stores: written once, never read -> keep L2 for the grid
        __stcs(&out_grads[3*m+0], grx);
        __stcs(&out_grads[3*m+1], gry);
        __stcs(&out_grads[3*m+2], grz);
    }

    // unit normal (IEEE ops)
    const float gl = __fsqrt_rn(__fadd_rn(__fadd_rn(__fmul_rn(grx,grx),
                        __fmul_rn(gry,gry)), __fmul_rn(grz,grz)));
    const float den = fmaxf(gl, 1e-12f);
    const float nx = __fdiv_rn(grx, den);
    const float ny = __fdiv_rn(gry, den);
    const float nz = __fdiv_rn(grz, den);

    // Laplace CDF density
    const float beta_eff = MIN_BETA + fabsf(beta[0]);
    const float inv_beta = 1.0f / beta_eff;
    const float sgn = (sdf > 0.0f) ? 1.0f : ((sdf < 0.0f) ? -1.0f : 0.0f);
    float sigma = inv_beta * (0.5f + 0.5f * sgn * expm1f(-fabsf(sdf) * inv_beta));
    if (!mask) sigma = 0.0f;
    const float tau = sigma * dt;

    // ---- 2-warp exclusive prefix of tau over 64 samples ----
    float x = tau;
    #pragma unroll
    for (int o = 1; o < 32; o <<= 1) {
        float y = __shfl_up_sync(0xFFFFFFFFu, x, o);
        if (lane >= o) x += y;
    }
    if (lane == 31) warp_tot[warp] = x;
    __syncthreads();
    float excl = x - tau;
    if (s >= 32) excl += warp_tot[warp - 1];

    const float T = expf(-excl);
    const float a = -expm1f(-tau);
    const float w = T * a;

    // ---- composite ----
    float acc[8];
    acc[0] = w * feat1;
    acc[1] = w * feat2;
    acc[2] = w * feat3;
    acc[3] = w * nx;
    acc[4] = w * ny;
    acc[5] = w * nz;
    acc[6] = w * t_mid;
    acc[7] = w;

    #pragma unroll
    for (int o = 16; o >= 1; o >>= 1) {
        #pragma unroll
        for (int k = 0; k < 8; k++)
            acc[k] += __shfl_xor_sync(0xFFFFFFFFu, acc[k], o);
    }
    if (lane == 0) {
        #pragma unroll
        for (int k = 0; k < 8; k++) red[warp][k] = acc[k];
    }
    __syncthreads();

    if ((tid & 63) == 0 && valid) {
        float r0 = red[warp][0] + red[warp+1][0];
        float r1 = red[warp][1] + red[warp+1][1];
        float r2 = red[warp][2] + red[warp+1][2];
        float r3 = red[warp][3] + red[warp+1][3];
        float r4 = red[warp][4] + red[warp+1][4];
        float r5 = red[warp][5] + red[warp+1][5];
        float r6 = red[warp][6] + red[warp+1][6];
        float r7 = red[warp][7] + red[warp+1][7];
        const float rdn = rays_d_norm[n];
        __stcs(&out_rgb[3*n+0], r0);
        __stcs(&out_rgb[3*n+1], r1);
        __stcs(&out_rgb[3*n+2], r2);
        __stcs(&out_depth[n],   __fdiv_rn(r6, rdn));
        __stcs(&out_normals[3*n+0], r3);
        __stcs(&out_normals[3*n+1], r4);
        __stcs(&out_normals[3*n+2], r5);
        __stcs(&out_acc[n],  r7);
        __stcs(&out_near[n], __fdiv_rn(nr, rdn));
        __stcs(&out_far[n],  __fdiv_rn(fr, rdn));
    }
}

extern "C" void kernel_launch(void* const* d_in, const int* in_sizes, int n_in,
                              void* d_out, int out_size) {
    const float* grid        = (const float*)d_in[0];
    const float* beta        = (const float*)d_in[1];
    const float* rays_o      = (const float*)d_in[2];
    const float* rays_d      = (const float*)d_in[3];
    const float* rays_d_norm = (const float*)d_in[4];
    const float* nearp       = (const float*)d_in[5];
    const float* farp        = (const float*)d_in[6];

    const int N = in_sizes[2] / 3;

    float* out = (float*)d_out;
    float* out_rgb     = out;
    float* out_depth   = out_rgb + (size_t)3 * N;
    float* out_normals = out_depth + N;
    float* out_acc     = out_normals + (size_t)3*N;
    float* out_grads   = out_acc + N;
    float* out_near    = out_grads + (size_t)3 * N * NS;
    float* out_far     = out_near + N;

    const int threads = 128;
    const int blocks  = (N * NS + threads - 1) / threads;
    plainvoxels_render_kernel<<<blocks, threads>>>(
        grid, beta, rays_o, rays_d, rays_d_norm, nearp, farp,
        out_rgb, out_depth, out_normals, out_acc, out_grads, out_near, out_far, N);
}